// round 11
// baseline (speedup 1.0000x reference)
#include <cuda_runtime.h>
#include <cuda_bf16.h>
#include <cstdint>

// Problem constants
#define NN 100000           // nodes
#define NR 4                // relations
#define NE 500000           // edges per relation
#define DD 128              // feature dim (in == out)
#define PAD 32              // max edges per (relation, dst) bucket in padded CSR
#define OVF_CAP 2048        // fallback list capacity for bucket overflow

// Scratch (device globals: allocation-free rule)
__device__ int g_cnt[NR * NN];                 // per-(r,dst) edge counts (== degree)
__device__ int g_slot[(size_t)NR * NN * PAD];  // padded CSR: src indices
__device__ int g_ovf[OVF_CAP];                 // overflow edge ids (r*NE+e)
__device__ int g_ovf_n;

// ---------------------------------------------------------------------------
// f32x2 packed helpers (base sm_10x ISA)
__device__ __forceinline__ uint64_t pack2(float lo, float hi) {
    uint64_t d;
    asm("mov.b64 %0, {%1, %2};" : "=l"(d) : "f"(lo), "f"(hi));
    return d;
}
__device__ __forceinline__ uint64_t pack_rep(float v) {
    uint64_t d;
    asm("mov.b64 %0, {%1, %1};" : "=l"(d) : "f"(v));
    return d;
}
__device__ __forceinline__ void unpack2(float& lo, float& hi, uint64_t v) {
    asm("mov.b64 {%0, %1}, %2;" : "=f"(lo), "=f"(hi) : "l"(v));
}
__device__ __forceinline__ void ffma2(uint64_t& d, uint64_t a, uint64_t b) {
    asm("fma.rn.f32x2 %0, %1, %2, %3;" : "=l"(d) : "l"(a), "l"(b), "l"(d));
}

// ---------------------------------------------------------------------------
__global__ void k_zero_cnt() {
    int i = blockIdx.x * blockDim.x + threadIdx.x;
    if (i < NR * NN) g_cnt[i] = 0;
    if (i == 0) g_ovf_n = 0;
}

// Build padded bucket-CSR: slot[r][dst][c] = src. Overflow -> fallback list.
__global__ void k_fill(const int* __restrict__ src_idx,
                       const int* __restrict__ dst_idx) {
    int i = blockIdx.x * blockDim.x + threadIdx.x;
    if (i >= NR * NE) return;
    int r = i / NE;
    int dst = dst_idx[i];
    int c = atomicAdd(&g_cnt[r * NN + dst], 1);
    if (c < PAD) {
        g_slot[((size_t)r * NN + dst) * PAD + c] = src_idx[i];
    } else {
        int o = atomicAdd(&g_ovf_n, 1);
        if (o < OVF_CAP) g_ovf[o] = i;
    }
}

// ---------------------------------------------------------------------------
// Fused aggregate + GEMM + bias + ReLU.
// Block = 64 dst rows (32 row pairs). For each relation r:
//   each warp gathers/averages x rows for its 4 dst-pairs directly into the
//   packed smem A tile (As2[k][pair] = {agg[2p][k], agg[2p+1][k]}), W_r is
//   staged in Bs, then the FFMA2 GEMM accumulates into registers across r.
// Epilogue: += bias sum, ReLU, plain STG. No z intermediate, no atomics.
#define BM 64
#define AS_STRIDE 33                         // u64 per k-row (break bank conflicts)
#define AS_BYTES (DD * AS_STRIDE * 8)        // 33792
#define SMEM_TOTAL (AS_BYTES + DD * DD * 4)  // + Bs 64KB = 99328

__global__ __launch_bounds__(256) void k_fused(const float* __restrict__ x,
                                               const float* __restrict__ W,
                                               const float* __restrict__ b,
                                               const int* __restrict__ src_idx,
                                               const int* __restrict__ dst_idx,
                                               float* __restrict__ out) {
    extern __shared__ char smem[];
    uint64_t* As2 = (uint64_t*)smem;
    float* Bs = (float*)(smem + AS_BYTES);

    const int tid = threadIdx.x;
    const int wid = tid >> 5, lane = tid & 31;
    const int m0 = blockIdx.x * BM;

    // Per-lane bias sums for cols lane*4 .. lane*4+3
    float bsum[4];
#pragma unroll
    for (int j = 0; j < 4; j++) {
        int c = lane * 4 + j;
        bsum[j] = b[c] + b[DD + c] + b[2 * DD + c] + b[3 * DD + c];
    }
    const int ovfn = min(g_ovf_n, OVF_CAP);   // typically 0

    uint64_t acc[4][4];
#pragma unroll
    for (int i = 0; i < 4; i++)
#pragma unroll
        for (int j = 0; j < 4; j++) acc[i][j] = 0ull;

    for (int r = 0; r < NR; r++) {
        __syncthreads();   // prior GEMM done reading Bs/As2 (no-op first iter)

        // ---- Stage W_r into Bs (coalesced)
        {
            const float4* Wv = (const float4*)(W + (size_t)r * DD * DD);
            float4* Bv = (float4*)Bs;
#pragma unroll
            for (int i = 0; i < 16; i++) Bv[i * 256 + tid] = Wv[i * 256 + tid];
        }

        // ---- Gather + average + pack: warp owns pairs wid*4 .. wid*4+3
#pragma unroll
        for (int pp = 0; pp < 4; pp++) {
            int p = wid * 4 + pp;
            int d0 = m0 + 2 * p, d1 = d0 + 1;
            float4 s0 = make_float4(0.f, 0.f, 0.f, 0.f);
            float4 s1 = make_float4(0.f, 0.f, 0.f, 0.f);
            int c0 = 0, c1 = 0;
            if (d0 < NN) {
                c0 = g_cnt[r * NN + d0];               // warp-uniform
                int n0 = min(c0, PAD);
                const int* sl = g_slot + ((size_t)r * NN + d0) * PAD;
                for (int j = 0; j < n0; j++) {
                    float4 v = ((const float4*)(x + (size_t)sl[j] * DD))[lane];
                    s0.x += v.x; s0.y += v.y; s0.z += v.z; s0.w += v.w;
                }
            }
            if (d1 < NN) {
                c1 = g_cnt[r * NN + d1];
                int n1 = min(c1, PAD);
                const int* sl = g_slot + ((size_t)r * NN + d1) * PAD;
                for (int j = 0; j < n1; j++) {
                    float4 v = ((const float4*)(x + (size_t)sl[j] * DD))[lane];
                    s1.x += v.x; s1.y += v.y; s1.z += v.z; s1.w += v.w;
                }
            }
            if (ovfn > 0) {                            // rare: bucket overflow
                for (int k = 0; k < ovfn; k++) {
                    int i = g_ovf[k];
                    if (i / NE == r) {
                        int dd = dst_idx[i];
                        if (dd == d0 || dd == d1) {
                            float4 v = ((const float4*)(x + (size_t)src_idx[i] * DD))[lane];
                            if (dd == d0) { s0.x += v.x; s0.y += v.y; s0.z += v.z; s0.w += v.w; }
                            else          { s1.x += v.x; s1.y += v.y; s1.z += v.z; s1.w += v.w; }
                        }
                    }
                }
            }
            float i0 = 1.0f / (float)max(c0, 1);
            float i1 = 1.0f / (float)max(c1, 1);
            s0.x *= i0; s0.y *= i0; s0.z *= i0; s0.w *= i0;
            s1.x *= i1; s1.y *= i1; s1.z *= i1; s1.w *= i1;
            // pack row pair into As2 (lane owns k = lane*4 .. lane*4+3)
            As2[(lane * 4 + 0) * AS_STRIDE + p] = pack2(s0.x, s1.x);
            As2[(lane * 4 + 1) * AS_STRIDE + p] = pack2(s0.y, s1.y);
            As2[(lane * 4 + 2) * AS_STRIDE + p] = pack2(s0.z, s1.z);
            As2[(lane * 4 + 3) * AS_STRIDE + p] = pack2(s0.w, s1.w);
        }
        __syncthreads();   // Bs staged + As2 visible across lanes

        // ---- GEMM accumulate (FFMA2): acc[i][c] += agg_pair_i[k] * W_r[k][c]
        const uint64_t* arow = As2 + wid * 4;
        const float4* brow = (const float4*)Bs + lane;
#pragma unroll 16
        for (int k = 0; k < DD; k++) {
            uint64_t a0 = arow[k * AS_STRIDE + 0];   // broadcast LDS64
            uint64_t a1 = arow[k * AS_STRIDE + 1];
            uint64_t a2 = arow[k * AS_STRIDE + 2];
            uint64_t a3 = arow[k * AS_STRIDE + 3];
            float4 bv = brow[k * 32];                // LDS128, conflict-free
            uint64_t b0 = pack_rep(bv.x), b1 = pack_rep(bv.y);
            uint64_t b2 = pack_rep(bv.z), b3 = pack_rep(bv.w);
            ffma2(acc[0][0], a0, b0); ffma2(acc[0][1], a0, b1);
            ffma2(acc[0][2], a0, b2); ffma2(acc[0][3], a0, b3);
            ffma2(acc[1][0], a1, b0); ffma2(acc[1][1], a1, b1);
            ffma2(acc[1][2], a1, b2); ffma2(acc[1][3], a1, b3);
            ffma2(acc[2][0], a2, b0); ffma2(acc[2][1], a2, b1);
            ffma2(acc[2][2], a2, b2); ffma2(acc[2][3], a2, b3);
            ffma2(acc[3][0], a3, b0); ffma2(acc[3][1], a3, b1);
            ffma2(acc[3][2], a3, b2); ffma2(acc[3][3], a3, b3);
        }
    }

    // ---- Epilogue: bias + ReLU, two rows per acc group, plain STG
#pragma unroll
    for (int ip = 0; ip < 4; ip++) {
        int re = m0 + wid * 8 + ip * 2;
        float4 lo, hi;
        unpack2(lo.x, hi.x, acc[ip][0]);
        unpack2(lo.y, hi.y, acc[ip][1]);
        unpack2(lo.z, hi.z, acc[ip][2]);
        unpack2(lo.w, hi.w, acc[ip][3]);
        lo.x = fmaxf(lo.x + bsum[0], 0.f); lo.y = fmaxf(lo.y + bsum[1], 0.f);
        lo.z = fmaxf(lo.z + bsum[2], 0.f); lo.w = fmaxf(lo.w + bsum[3], 0.f);
        hi.x = fmaxf(hi.x + bsum[0], 0.f); hi.y = fmaxf(hi.y + bsum[1], 0.f);
        hi.z = fmaxf(hi.z + bsum[2], 0.f); hi.w = fmaxf(hi.w + bsum[3], 0.f);
        if (re < NN)     ((float4*)(out + (size_t)re * DD))[lane] = lo;
        if (re + 1 < NN) ((float4*)(out + (size_t)(re + 1) * DD))[lane] = hi;
    }
}

// ---------------------------------------------------------------------------
extern "C" void kernel_launch(void* const* d_in, const int* in_sizes, int n_in,
                              void* d_out, int out_size) {
    const float* x = (const float*)d_in[0];      // [100000,128]
    const float* W = (const float*)d_in[1];      // [4,128,128]
    const float* b = (const float*)d_in[2];      // [4,128]
    const int* src_idx = (const int*)d_in[3];    // [4,500000]
    const int* dst_idx = (const int*)d_in[4];    // [4,500000]
    float* out = (float*)d_out;                  // [100000,128]

    cudaFuncSetAttribute(k_fused, cudaFuncAttributeMaxDynamicSharedMemorySize,
                         SMEM_TOTAL);

    // Build padded bucket-CSR (counts double as degrees).
    k_zero_cnt<<<(NR * NN + 255) / 256, 256>>>();
    k_fill<<<(NR * NE + 255) / 256, 256>>>(src_idx, dst_idx);

    // Fused aggregate -> GEMM -> bias -> ReLU. Writes every out row.
    int mtiles = (NN + BM - 1) / BM;             // 1563
    k_fused<<<mtiles, 256, SMEM_TOTAL>>>(x, W, b, src_idx, dst_idx, out);
}

// round 12
// speedup vs baseline: 1.7836x; 1.7836x over previous
#include <cuda_runtime.h>
#include <cuda_fp16.h>
#include <cstdint>

// Problem constants
#define NN 100000           // nodes
#define NR 4                // relations
#define NE 500000           // edges per relation
#define DD 128              // feature dim (in == out)
#define PAD 32              // max edges per (relation, dst) bucket in padded CSR
#define OVF_CAP 2048        // fallback list capacity for bucket overflow

// Scratch (device globals: allocation-free rule)
__device__ __half2 g_zh[(size_t)NR * NN * (DD / 2)];  // z in fp16: [r][n][64xhalf2] (~102MB)
__device__ int g_cnt[NR * NN];                 // per-(r,dst) edge counts (== degree)
__device__ int g_slot[(size_t)NR * NN * PAD];  // padded CSR: src indices
__device__ int g_ovf[OVF_CAP];                 // overflow edge ids (r*NE+e)
__device__ int g_ovf_n;

// ---------------------------------------------------------------------------
// f32x2 packed helpers (base sm_10x ISA)
__device__ __forceinline__ uint64_t pack2(float lo, float hi) {
    uint64_t d;
    asm("mov.b64 %0, {%1, %2};" : "=l"(d) : "f"(lo), "f"(hi));
    return d;
}
__device__ __forceinline__ uint64_t pack_rep(float v) {
    uint64_t d;
    asm("mov.b64 %0, {%1, %1};" : "=l"(d) : "f"(v));
    return d;
}
__device__ __forceinline__ void unpack2(float& lo, float& hi, uint64_t v) {
    asm("mov.b64 {%0, %1}, %2;" : "=f"(lo), "=f"(hi) : "l"(v));
}
__device__ __forceinline__ void ffma2(uint64_t& d, uint64_t a, uint64_t b) {
    asm("fma.rn.f32x2 %0, %1, %2, %3;" : "=l"(d) : "l"(a), "l"(b), "l"(d));
}

// ---------------------------------------------------------------------------
__global__ void k_zero_cnt() {
    int i = blockIdx.x * blockDim.x + threadIdx.x;
    if (i < NR * NN) g_cnt[i] = 0;
    if (i == 0) g_ovf_n = 0;
}

// Build padded bucket-CSR: slot[r][dst][c] = src. Overflow -> fallback list.
__global__ void k_fill(const int* __restrict__ src_idx,
                       const int* __restrict__ dst_idx) {
    int i = blockIdx.x * blockDim.x + threadIdx.x;
    if (i >= NR * NE) return;
    int r = i / NE;
    int dst = dst_idx[i];
    int c = atomicAdd(&g_cnt[r * NN + dst], 1);
    if (c < PAD) {
        g_slot[((size_t)r * NN + dst) * PAD + c] = src_idx[i];
    } else {
        int o = atomicAdd(&g_ovf_n, 1);
        if (o < OVF_CAP) g_ovf[o] = i;
    }
}

// ---------------------------------------------------------------------------
// GEMM: for r in 0..3: z[r][m0:m0+64] = x_tile @ W[r], z stored fp16.
// A row-pair-packed in smem; fma.rn.f32x2 computes two output rows/instr.
#define BM 64
#define AS_STRIDE 33                         // u64 per k-row (break bank conflicts)
#define AS_BYTES (DD * AS_STRIDE * 8)        // 33792
#define SMEM_TOTAL (AS_BYTES + DD * DD * 4)  // + Bs 64KB = 99328

__global__ __launch_bounds__(256) void k_gemm3(const float* __restrict__ x,
                                               const float* __restrict__ W) {
    extern __shared__ char smem[];
    uint64_t* As2 = (uint64_t*)smem;
    float* Bs = (float*)(smem + AS_BYTES);

    const int tid = threadIdx.x;
    const int wid = tid >> 5, lane = tid & 31;
    const int m0 = blockIdx.x * BM;

    // ---- Load x tile (64 rows x 128 k), pack row pairs, transpose into As2.
#pragma unroll
    for (int pass = 0; pass < 4; pass++) {
        int idx = pass * 256 + tid;
        int p = idx >> 5;
        int k4 = idx & 31;
        int r0 = m0 + 2 * p;
        float4 v0 = make_float4(0.f, 0.f, 0.f, 0.f), v1 = v0;
        if (r0 < NN)     v0 = ((const float4*)(x + (size_t)r0 * DD))[k4];
        if (r0 + 1 < NN) v1 = ((const float4*)(x + (size_t)(r0 + 1) * DD))[k4];
        As2[(k4 * 4 + 0) * AS_STRIDE + p] = pack2(v0.x, v1.x);
        As2[(k4 * 4 + 1) * AS_STRIDE + p] = pack2(v0.y, v1.y);
        As2[(k4 * 4 + 2) * AS_STRIDE + p] = pack2(v0.z, v1.z);
        As2[(k4 * 4 + 3) * AS_STRIDE + p] = pack2(v0.w, v1.w);
    }

    for (int r = 0; r < NR; r++) {
        // ---- Load W[r] (128x128 fp32, row-major [k][n]) into Bs, coalesced.
        {
            const float4* Wv = (const float4*)(W + (size_t)r * DD * DD);
            float4* Bv = (float4*)Bs;
#pragma unroll
            for (int i = 0; i < 16; i++) Bv[i * 256 + tid] = Wv[i * 256 + tid];
        }
        __syncthreads();

        uint64_t acc[4][4];
#pragma unroll
        for (int i = 0; i < 4; i++)
#pragma unroll
            for (int j = 0; j < 4; j++) acc[i][j] = 0ull;

        const uint64_t* arow = As2 + wid * 4;
        const float4* brow = (const float4*)Bs + lane;

#pragma unroll 16
        for (int k = 0; k < DD; k++) {
            uint64_t a0 = arow[k * AS_STRIDE + 0];   // broadcast LDS64
            uint64_t a1 = arow[k * AS_STRIDE + 1];
            uint64_t a2 = arow[k * AS_STRIDE + 2];
            uint64_t a3 = arow[k * AS_STRIDE + 3];
            float4 bv = brow[k * 32];                // LDS128, conflict-free
            uint64_t b0 = pack_rep(bv.x), b1 = pack_rep(bv.y);
            uint64_t b2 = pack_rep(bv.z), b3 = pack_rep(bv.w);
            ffma2(acc[0][0], a0, b0); ffma2(acc[0][1], a0, b1);
            ffma2(acc[0][2], a0, b2); ffma2(acc[0][3], a0, b3);
            ffma2(acc[1][0], a1, b0); ffma2(acc[1][1], a1, b1);
            ffma2(acc[1][2], a1, b2); ffma2(acc[1][3], a1, b3);
            ffma2(acc[2][0], a2, b0); ffma2(acc[2][1], a2, b1);
            ffma2(acc[2][2], a2, b2); ffma2(acc[2][3], a2, b3);
            ffma2(acc[3][0], a3, b0); ffma2(acc[3][1], a3, b1);
            ffma2(acc[3][2], a3, b2); ffma2(acc[3][3], a3, b3);
        }
        __syncthreads();

        // ---- Epilogue: unpack pairs, convert fp16, store two rows per group.
        // Row layout: 32 uint2 per row (uint2 = 2x half2 = 4 cols); lane -> uint2 lane.
        uint2* zr = (uint2*)(g_zh + ((size_t)r * NN) * (DD / 2));
#pragma unroll
        for (int ip = 0; ip < 4; ip++) {
            int re = m0 + wid * 8 + ip * 2;
            float4 lo, hi;
            unpack2(lo.x, hi.x, acc[ip][0]);
            unpack2(lo.y, hi.y, acc[ip][1]);
            unpack2(lo.z, hi.z, acc[ip][2]);
            unpack2(lo.w, hi.w, acc[ip][3]);
            if (re < NN) {
                __half2 h01 = __floats2half2_rn(lo.x, lo.y);
                __half2 h23 = __floats2half2_rn(lo.z, lo.w);
                uint2 u; u.x = *(uint32_t*)&h01; u.y = *(uint32_t*)&h23;
                zr[(size_t)re * 32 + lane] = u;
            }
            if (re + 1 < NN) {
                __half2 h01 = __floats2half2_rn(hi.x, hi.y);
                __half2 h23 = __floats2half2_rn(hi.z, hi.w);
                uint2 u; u.x = *(uint32_t*)&h01; u.y = *(uint32_t*)&h23;
                zr[(size_t)(re + 1) * 32 + lane] = u;
            }
        }
    }
}

// ---------------------------------------------------------------------------
// Gather-scatter, de-atomicized: one warp per dst node. For each relation,
// accumulate bucket edges' fp16 z rows in fp32 registers, scale by 1/deg,
// sum over relations, single plain STG per output row.
__global__ __launch_bounds__(256) void k_scatter2(float* __restrict__ out) {
    int gw = blockIdx.x * (blockDim.x >> 5) + (threadIdx.x >> 5);   // dst node
    int lane = threadIdx.x & 31;
    if (gw >= NN) return;

    float4 tot = make_float4(0.f, 0.f, 0.f, 0.f);
#pragma unroll
    for (int r = 0; r < NR; r++) {
        int cnt = g_cnt[r * NN + gw];                 // warp-uniform broadcast
        int n = min(cnt, PAD);
        const int* sl = g_slot + ((size_t)r * NN + gw) * PAD;
        const uint2* zr = (const uint2*)(g_zh + ((size_t)r * NN) * (DD / 2));
        float4 acc = make_float4(0.f, 0.f, 0.f, 0.f);
        for (int j = 0; j < n; j++) {
            int src = sl[j];                          // warp-uniform broadcast
            uint2 u = zr[(size_t)src * 32 + lane];    // 8B per lane (4 fp16 cols)
            float2 f01 = __half22float2(*(__half2*)&u.x);
            float2 f23 = __half22float2(*(__half2*)&u.y);
            acc.x += f01.x; acc.y += f01.y; acc.z += f23.x; acc.w += f23.y;
        }
        float inv = 1.0f / (float)max(cnt, 1);
        tot.x += acc.x * inv; tot.y += acc.y * inv;
        tot.z += acc.z * inv; tot.w += acc.w * inv;
    }
    ((float4*)(out + (size_t)gw * DD))[lane] = tot;
}

// Overflow fallback: one warp per overflow edge (rarely any). red.add into out.
__global__ __launch_bounds__(256) void k_scatter_ovf2(const int* __restrict__ src_idx,
                                                      const int* __restrict__ dst_idx,
                                                      float* __restrict__ out) {
    int w = blockIdx.x * (blockDim.x >> 5) + (threadIdx.x >> 5);
    int lane = threadIdx.x & 31;
    int n = min(g_ovf_n, OVF_CAP);
    if (w >= n) return;
    int i = g_ovf[w];                  // edge id = r*NE + e
    int r = i / NE;
    int src = src_idx[i];
    int dst = dst_idx[i];
    float inv = 1.0f / (float)max(g_cnt[r * NN + dst], 1);
    const uint2 u = ((const uint2*)(g_zh + ((size_t)r * NN) * (DD / 2)))[(size_t)src * 32 + lane];
    float2 f01 = __half22float2(*(__half2*)&u.x);
    float2 f23 = __half22float2(*(__half2*)&u.y);
    float* p = out + (size_t)dst * DD + lane * 4;
    asm volatile("red.global.add.v4.f32 [%0], {%1,%2,%3,%4};"
                 :: "l"(p), "f"(f01.x * inv), "f"(f01.y * inv),
                    "f"(f23.x * inv), "f"(f23.y * inv)
                 : "memory");
}

// ---------------------------------------------------------------------------
__global__ void k_relu_bias(float* __restrict__ out, const float* __restrict__ b) {
    __shared__ float bs[DD];
    if (threadIdx.x < DD) {
        bs[threadIdx.x] = b[threadIdx.x] + b[DD + threadIdx.x] +
                          b[2 * DD + threadIdx.x] + b[3 * DD + threadIdx.x];
    }
    __syncthreads();
    size_t i4 = (size_t)blockIdx.x * blockDim.x + threadIdx.x;
    size_t total4 = (size_t)NN * DD / 4;
    if (i4 >= total4) return;
    int col = (int)((i4 * 4) & (DD - 1));
    float4* p = (float4*)out + i4;
    float4 v = *p;
    v.x = fmaxf(v.x + bs[col + 0], 0.f);
    v.y = fmaxf(v.y + bs[col + 1], 0.f);
    v.z = fmaxf(v.z + bs[col + 2], 0.f);
    v.w = fmaxf(v.w + bs[col + 3], 0.f);
    *p = v;
}

// ---------------------------------------------------------------------------
extern "C" void kernel_launch(void* const* d_in, const int* in_sizes, int n_in,
                              void* d_out, int out_size) {
    const float* x = (const float*)d_in[0];      // [100000,128]
    const float* W = (const float*)d_in[1];      // [4,128,128]
    const float* b = (const float*)d_in[2];      // [4,128]
    const int* src_idx = (const int*)d_in[3];    // [4,500000]
    const int* dst_idx = (const int*)d_in[4];    // [4,500000]
    float* out = (float*)d_out;                  // [100000,128]

    cudaFuncSetAttribute(k_gemm3, cudaFuncAttributeMaxDynamicSharedMemorySize,
                         SMEM_TOTAL);

    // Build padded bucket-CSR (counts double as degrees).
    k_zero_cnt<<<(NR * NN + 255) / 256, 256>>>();
    k_fill<<<(NR * NE + 255) / 256, 256>>>(src_idx, dst_idx);

    // z[r] = x @ W[r] (fp16 store), all relations per block
    int mtiles = (NN + BM - 1) / BM;             // 1563
    k_gemm3<<<mtiles, 256, SMEM_TOTAL>>>(x, W);

    // De-atomicized gather-accumulate: one warp per dst row, plain STG.
    k_scatter2<<<(NN + 7) / 8, 256>>>(out);

    // Rare bucket-overflow edges (usually zero) accumulate atomically.
    k_scatter_ovf2<<<(OVF_CAP / 8 + 1), 256>>>(src_idx, dst_idx, out);

    // Bias + ReLU
    size_t total4 = (size_t)NN * DD / 4;
    k_relu_bias<<<(int)((total4 + 255) / 256), 256>>>(out, b);
}